// round 17
// baseline (speedup 1.0000x reference)
#include <cuda_runtime.h>
#include <cuda_fp16.h>
#include <cstdint>

// ===========================================================================
// VAE decoder, sm_103 fallback tensor path, fp16 mma.sync m16n8k16 (fp32 acc).
// L1-L4: BM128 x BN256 block tile, 64x64 warp tiles, 1 CTA/SM, 4-stage
// cp.async pipeline, ldmatrix.x4. L5: 64x32 warp-tile variant (N=256).
// L2 expert sum via fp32 per-expert planes + vectorized reduce.
// GEMMs: A[M,K] row * W[N,K] row^T -> C[M,N], M=4096, K%32==0.
// ===========================================================================

#define BROWS 4096
#define BK 32
#define LDSKH 40                          // halfs/row: 80B, conflict-free LDSM
// --- wide kernel (L1-L4): BM=128, BN=256 ---
#define W_OPA (128 * LDSKH * 2)           // 10240 B
#define W_OPB (256 * LDSKH * 2)           // 20480 B
#define W_STG (W_OPA + W_OPB)             // 30720 B
#define W_STAGES 4
// --- narrow kernel (L5): BM=128, BN=128 ---
#define N_OP  (128 * LDSKH * 2)
#define N_STG (2 * N_OP)                  // 20480 B
#define N_STAGES 4

// ---- scratch (device globals; allocation-free) ----------------------------
__device__ __align__(128) __half g_X  [(size_t)BROWS * 2368];
__device__ __align__(128) __half g_H1 [(size_t)8 * BROWS * 2048];
__device__ __align__(128) __half g_W1h[(size_t)8 * 2048 * 2368];
__device__ __align__(128) __half g_W2h[(size_t)8 * 2560 * 2048];   // N pad 2560
__device__ __align__(128) __half g_W3h[(size_t)2048 * 2496];
__device__ __align__(128) __half g_W4h[(size_t)2560 * 2176];       // N pad 2560
__device__ __align__(128) __half g_W5h[(size_t)256 * 2496];
__device__ __align__(128) __half g_bufC[(size_t)BROWS * 2496];     // L2 sum + z
__device__ __align__(128) __half g_bufD[(size_t)BROWS * 2176];     // L3 out + z
__device__ __align__(128) __half g_bufE[(size_t)BROWS * 2496];     // L4 out + z
__device__ __align__(128) float  g_E2 [(size_t)8 * BROWS * 2368];  // fp32 planes

// ---- helpers --------------------------------------------------------------
__device__ __forceinline__ float elu1(float x) { return x > 0.f ? x : expm1f(x); }
__device__ __forceinline__ uint32_t smem_u32(const void* p) {
    uint32_t a;
    asm("{ .reg .u64 t; cvta.to.shared.u64 t, %1; cvt.u32.u64 %0, t; }" : "=r"(a) : "l"(p));
    return a;
}
__device__ __forceinline__ void cp16(uint32_t d, const void* s) {
    asm volatile("cp.async.cg.shared.global [%0], [%1], 16;" :: "r"(d), "l"(s) : "memory");
}
__device__ __forceinline__ void cp_commit() {
    asm volatile("cp.async.commit_group;" ::: "memory");
}
__device__ __forceinline__ void cp_wait2() {
    asm volatile("cp.async.wait_group 2;" ::: "memory");
}
__device__ __forceinline__ void ldsm4(uint32_t r[4], uint32_t addr) {
    asm volatile("ldmatrix.sync.aligned.m8n8.x4.shared.b16 {%0,%1,%2,%3}, [%4];"
        : "=r"(r[0]), "=r"(r[1]), "=r"(r[2]), "=r"(r[3]) : "r"(addr));
}
__device__ __forceinline__ void mma_fp16(float c[4], const uint32_t a[4],
                                         uint32_t b0, uint32_t b1) {
    asm volatile(
        "mma.sync.aligned.m16n8k16.row.col.f32.f16.f16.f32 "
        "{%0,%1,%2,%3}, {%4,%5,%6,%7}, {%8,%9}, {%0,%1,%2,%3};\n"
        : "+f"(c[0]), "+f"(c[1]), "+f"(c[2]), "+f"(c[3])
        : "r"(a[0]), "r"(a[1]), "r"(a[2]), "r"(a[3]), "r"(b0), "r"(b1));
}
__device__ __forceinline__ void store4h(__half* p, float4 v) {
    half2 h0 = __floats2half2_rn(v.x, v.y);
    half2 h1 = __floats2half2_rn(v.z, v.w);
    uint2 u;
    u.x = *(uint32_t*)&h0; u.y = *(uint32_t*)&h1;
    *(uint2*)p = u;
}
__device__ __forceinline__ void store2(float* p, float a, float b) {
    *(float2*)p = make_float2(a, b);
}
__device__ __forceinline__ void store2(__half* p, float a, float b) {
    *(half2*)p = __floats2half2_rn(a, b);
}

// ---- prep kernels ---------------------------------------------------------
__global__ void cvt_rows(const float* __restrict__ src, __half* __restrict__ dst,
                         int N, int K)
{
    const int row = blockIdx.x, e = blockIdx.y;
    const int Npad = gridDim.x;
    const int n4 = K >> 2;
    __half* d = dst + ((size_t)e * Npad + row) * K;
    if (row < N) {
        const float4* s = (const float4*)(src + ((size_t)e * N + row) * K);
        for (int i = threadIdx.x; i < n4; i += blockDim.x) store4h(d + 4*i, s[i]);
    } else {
        const float4 zz = make_float4(0.f, 0.f, 0.f, 0.f);
        for (int i = threadIdx.x; i < n4; i += blockDim.x) store4h(d + 4*i, zz);
    }
}

__global__ void pack_kernel(const float* __restrict__ motions,
                            const float* __restrict__ angles,
                            const float* __restrict__ z,
                            const float* __restrict__ l5_w)
{
    const int b = blockIdx.x;
    __half* X = g_X + (size_t)b * 2368;
    const float4* m4 = (const float4*)(motions + (size_t)b * 1792);
    const float4* a4 = (const float4*)(angles + (size_t)b * 448);
    const float4* z4 = (const float4*)(z + (size_t)b * 128);
    for (int i = threadIdx.x; i < 592; i += blockDim.x) {
        float4 v = (i < 448) ? m4[i] : (i < 560) ? a4[i - 448] : z4[i - 560];
        store4h(X + 4*i, v);
    }
    for (int i = threadIdx.x; i < 32; i += blockDim.x) {
        float4 v = z4[i];
        store4h(g_bufC + (size_t)b * 2496 + 2368 + 4*i, v);
        store4h(g_bufD + (size_t)b * 2176 + 2048 + 4*i, v);
        store4h(g_bufE + (size_t)b * 2496 + 2368 + 4*i, v);
    }
    if (b < 256) {
        const float4* s = (const float4*)(l5_w + (size_t)b * 2496);
        __half* d = g_W5h + (size_t)b * 2496;
        for (int i = threadIdx.x; i < 624; i += blockDim.x) store4h(d + 4*i, s[i]);
    }
}

__global__ void reduce_kernel()
{
    const int b = blockIdx.x;
    __half* dst = g_bufC + (size_t)b * 2496;
    for (int i = threadIdx.x; i < 592; i += blockDim.x) {
        float4 s = make_float4(0.f, 0.f, 0.f, 0.f);
        #pragma unroll
        for (int e = 0; e < 8; e++) {
            float4 v = ((const float4*)(g_E2 + ((size_t)e * BROWS + b) * 2368))[i];
            s.x += v.x; s.y += v.y; s.z += v.z; s.w += v.w;
        }
        store4h(dst + 4*i, s);
    }
}

// ---- wide GEMM: BM128 x BN256, 64x64 warp tiles, 1 CTA/SM -----------------
template<bool PARA, typename OutT>
__global__ void __launch_bounds__(256, 1)
gemm_wide(const __half* __restrict__ A0, int lda, size_t sAe,
          const __half* __restrict__ W0, size_t sWe,
          const float* __restrict__ bias0, int sBe,
          const float* __restrict__ para,
          OutT* __restrict__ C0, int ldc, size_t sCe,
          int N, int K)
{
    extern __shared__ __half smem[];
    const uint32_t sbase = smem_u32(smem);

    const int tid = threadIdx.x;
    const int lane = tid & 31, warp = tid >> 5;
    const int warpM = warp & 1, warpN = warp >> 1;       // 2 x 4, tile 64x64
    const int g = lane >> 2, tg = lane & 3;
    const int mBlock = blockIdx.y * 128;
    const int nBlock = blockIdx.x * 256;
    const int e = blockIdx.z;
    const int Kiters = K / BK;

    const __half* A = A0 + (size_t)e * sAe;
    const __half* W = W0 + (size_t)e * sWe;

    const int cr = tid >> 2;          // 0..63
    const int ccB = (tid & 3) * 16;   // byte offset within 64B k-row
    const int ch = (tid & 3) * 8;     // half offset

    const int r8 = lane & 7, sel = lane >> 3;
    const uint32_t frag_off =
        (uint32_t)((((sel & 1) * 8 + r8) * LDSKH + (sel >> 1) * 8) * 2);

    auto issue = [&](int stage, int kt) {
        uint32_t sa = sbase + stage * W_STG;
        #pragma unroll
        for (int i = 0; i < 2; i++) {
            int r = cr + i * 64;
            cp16(sa + (uint32_t)(r * (LDSKH * 2)) + ccB,
                 A + (size_t)(mBlock + r) * lda + kt * BK + ch);
        }
        uint32_t sw = sa + W_OPA;
        #pragma unroll
        for (int i = 0; i < 4; i++) {
            int r = cr + i * 64;
            cp16(sw + (uint32_t)(r * (LDSKH * 2)) + ccB,
                 W + (size_t)(nBlock + r) * K + kt * BK + ch);
        }
    };

    float acc[4][8][4];
    #pragma unroll
    for (int mi = 0; mi < 4; mi++)
        #pragma unroll
        for (int ni = 0; ni < 8; ni++)
            #pragma unroll
            for (int c = 0; c < 4; c++) acc[mi][ni][c] = 0.f;

    #pragma unroll
    for (int s = 0; s < W_STAGES - 1; s++) {
        if (s < Kiters) issue(s, s);
        cp_commit();
    }

    for (int kt = 0; kt < Kiters; kt++) {
        cp_wait2();
        __syncthreads();

        int nxt = kt + W_STAGES - 1;
        if (nxt < Kiters) issue(nxt % W_STAGES, nxt);
        cp_commit();

        const int st = kt % W_STAGES;
        const uint32_t Ab = sbase + st * W_STG
                          + (uint32_t)(warpM * 64 * LDSKH * 2) + frag_off;
        const uint32_t Wb = sbase + st * W_STG + W_OPA
                          + (uint32_t)(warpN * 64 * LDSKH * 2) + frag_off;

        uint32_t a[2][4][4], b[2][4][4];
        #pragma unroll
        for (int ks = 0; ks < 2; ks++) {
            #pragma unroll
            for (int mi = 0; mi < 4; mi++)
                ldsm4(a[ks][mi], Ab + (uint32_t)(mi * 16 * LDSKH * 2) + ks * 32);
            #pragma unroll
            for (int p = 0; p < 4; p++)
                ldsm4(b[ks][p], Wb + (uint32_t)(p * 16 * LDSKH * 2) + ks * 32);
        }
        #pragma unroll
        for (int ks = 0; ks < 2; ks++)
            #pragma unroll
            for (int mi = 0; mi < 4; mi++)
                #pragma unroll
                for (int ni = 0; ni < 8; ni++)
                    mma_fp16(acc[mi][ni], a[ks][mi],
                             b[ks][ni >> 1][ni & 1], b[ks][ni >> 1][(ni & 1) + 2]);
    }

    const float* bias = bias0 + (size_t)e * sBe;
    const float pe = PARA ? para[e] : 1.0f;
    OutT* C = C0 + (size_t)e * sCe;
    #pragma unroll
    for (int ni = 0; ni < 8; ni++) {
        int col0 = nBlock + warpN * 64 + ni * 8 + tg * 2;
        if (col0 >= N) continue;
        float b0 = bias[col0];
        float b1 = bias[col0 + 1];
        #pragma unroll
        for (int mi = 0; mi < 4; mi++) {
            int r0 = mBlock + warpM * 64 + mi * 16 + g;
            store2(C + (size_t)r0 * ldc + col0,
                   elu1(acc[mi][ni][0] + b0) * pe, elu1(acc[mi][ni][1] + b1) * pe);
            store2(C + (size_t)(r0 + 8) * ldc + col0,
                   elu1(acc[mi][ni][2] + b0) * pe, elu1(acc[mi][ni][3] + b1) * pe);
        }
    }
}

// ---- narrow GEMM: BM128 x BN128, 64x32 warp tiles, 2 CTAs/SM (L5) ---------
template<typename OutT>
__global__ void __launch_bounds__(256, 2)
gemm_narrow(const __half* __restrict__ A0, int lda,
            const __half* __restrict__ W0,
            const float* __restrict__ bias0,
            OutT* __restrict__ C0, int ldc,
            int N, int K)
{
    extern __shared__ __half smem[];
    const uint32_t sbase = smem_u32(smem);

    const int tid = threadIdx.x;
    const int lane = tid & 31, warp = tid >> 5;
    const int warpM = warp & 1, warpN = warp >> 1;
    const int g = lane >> 2, tg = lane & 3;
    const int mBlock = blockIdx.y * 128;
    const int nBlock = blockIdx.x * 128;
    const int Kiters = K / BK;

    const int cr = tid >> 2;
    const int ccB = (tid & 3) * 16;
    const int ch = (tid & 3) * 8;

    const int r8 = lane & 7, sel = lane >> 3;
    const uint32_t frag_off =
        (uint32_t)((((sel & 1) * 8 + r8) * LDSKH + (sel >> 1) * 8) * 2);

    auto issue = [&](int stage, int kt) {
        uint32_t sa = sbase + stage * N_STG;
        #pragma unroll
        for (int i = 0; i < 2; i++) {
            int r = cr + i * 64;
            cp16(sa + (uint32_t)(r * (LDSKH * 2)) + ccB,
                 A0 + (size_t)(mBlock + r) * lda + kt * BK + ch);
        }
        uint32_t sw = sa + N_OP;
        #pragma unroll
        for (int i = 0; i < 2; i++) {
            int r = cr + i * 64;
            cp16(sw + (uint32_t)(r * (LDSKH * 2)) + ccB,
                 W0 + (size_t)(nBlock + r) * K + kt * BK + ch);
        }
    };

    float acc[4][4][4];
    #pragma unroll
    for (int mi = 0; mi < 4; mi++)
        #pragma unroll
        for (int ni = 0; ni < 4; ni++)
            #pragma unroll
            for (int c = 0; c < 4; c++) acc[mi][ni][c] = 0.f;

    #pragma unroll
    for (int s = 0; s < N_STAGES - 1; s++) {
        if (s < Kiters) issue(s, s);
        cp_commit();
    }

    for (int kt = 0; kt < Kiters; kt++) {
        cp_wait2();
        __syncthreads();

        int nxt = kt + N_STAGES - 1;
        if (nxt < Kiters) issue(nxt % N_STAGES, nxt);
        cp_commit();

        const int st = kt % N_STAGES;
        const uint32_t Ab = sbase + st * N_STG
                          + (uint32_t)(warpM * 64 * LDSKH * 2) + frag_off;
        const uint32_t Wb = sbase + st * N_STG + N_OP
                          + (uint32_t)(warpN * 32 * LDSKH * 2) + frag_off;
        #pragma unroll
        for (int ks = 0; ks < 2; ks++) {
            uint32_t a[4][4], b[2][4];
            #pragma unroll
            for (int mi = 0; mi < 4; mi++)
                ldsm4(a[mi], Ab + (uint32_t)(mi * 16 * LDSKH * 2) + ks * 32);
            #pragma unroll
            for (int p = 0; p < 2; p++)
                ldsm4(b[p], Wb + (uint32_t)(p * 16 * LDSKH * 2) + ks * 32);
            #pragma unroll
            for (int mi = 0; mi < 4; mi++)
                #pragma unroll
                for (int ni = 0; ni < 4; ni++)
                    mma_fp16(acc[mi][ni], a[mi],
                             b[ni >> 1][ni & 1], b[ni >> 1][(ni & 1) + 2]);
        }
    }

    #pragma unroll
    for (int ni = 0; ni < 4; ni++) {
        int col0 = nBlock + warpN * 32 + ni * 8 + tg * 2;
        if (col0 >= N) continue;
        float b0 = bias0[col0];
        float b1 = bias0[col0 + 1];
        #pragma unroll
        for (int mi = 0; mi < 4; mi++) {
            int r0 = mBlock + warpM * 64 + mi * 16 + g;
            store2(C0 + (size_t)r0 * ldc + col0,
                   elu1(acc[mi][ni][0] + b0), elu1(acc[mi][ni][1] + b1));
            store2(C0 + (size_t)(r0 + 8) * ldc + col0,
                   elu1(acc[mi][ni][2] + b0), elu1(acc[mi][ni][3] + b1));
        }
    }
}

// ---- launch ---------------------------------------------------------------
extern "C" void kernel_launch(void* const* d_in, const int* in_sizes, int n_in,
                              void* d_out, int out_size)
{
    const float* motions = (const float*)d_in[0];
    const float* angles  = (const float*)d_in[1];
    const float* z       = (const float*)d_in[2];
    const float* l1_w    = (const float*)d_in[3];
    const float* l1_b    = (const float*)d_in[4];
    const float* l2_w    = (const float*)d_in[5];
    const float* l2_b    = (const float*)d_in[6];
    const float* para    = (const float*)d_in[7];
    const float* l3_w    = (const float*)d_in[8];
    const float* l3_b    = (const float*)d_in[9];
    const float* l4_w    = (const float*)d_in[10];
    const float* l4_b    = (const float*)d_in[11];
    const float* l5_w    = (const float*)d_in[12];
    const float* l5_b    = (const float*)d_in[13];
    float* out = (float*)d_out;

    __half *X, *H1, *W1h, *W2h, *W3h, *W4h, *W5h, *bufC, *bufD, *bufE;
    float* E2;
    cudaGetSymbolAddress((void**)&X,    g_X);
    cudaGetSymbolAddress((void**)&H1,   g_H1);
    cudaGetSymbolAddress((void**)&W1h,  g_W1h);
    cudaGetSymbolAddress((void**)&W2h,  g_W2h);
    cudaGetSymbolAddress((void**)&W3h,  g_W3h);
    cudaGetSymbolAddress((void**)&W4h,  g_W4h);
    cudaGetSymbolAddress((void**)&W5h,  g_W5h);
    cudaGetSymbolAddress((void**)&bufC, g_bufC);
    cudaGetSymbolAddress((void**)&bufD, g_bufD);
    cudaGetSymbolAddress((void**)&bufE, g_bufE);
    cudaGetSymbolAddress((void**)&E2,   g_E2);

    const int SHW = W_STAGES * W_STG;   // 122880 B (1 CTA/SM)
    const int SHN = N_STAGES * N_STG;   // 81920 B (2 CTAs/SM)
    cudaFuncSetAttribute(gemm_wide<false, __half>, cudaFuncAttributeMaxDynamicSharedMemorySize, SHW);
    cudaFuncSetAttribute(gemm_wide<true,  float >, cudaFuncAttributeMaxDynamicSharedMemorySize, SHW);
    cudaFuncSetAttribute(gemm_narrow<float>,       cudaFuncAttributeMaxDynamicSharedMemorySize, SHN);

    pack_kernel<<<4096, 256>>>(motions, angles, z, l5_w);
    cvt_rows<<<dim3(2048, 8), 256>>>(l1_w, W1h, 2048, 2368);
    cvt_rows<<<dim3(2560, 8), 256>>>(l2_w, W2h, 2368, 2048);
    cvt_rows<<<dim3(2048, 1), 256>>>(l3_w, W3h, 2048, 2496);
    cvt_rows<<<dim3(2560, 1), 256>>>(l4_w, W4h, 2368, 2176);

    // L1: H1[e] = fp16(elu(X @ W1[e]^T + b1[e]))   K=2368, N=2048
    gemm_wide<false, __half><<<dim3(8, 32, 8), 256, SHW>>>(
        X, 2368, (size_t)0,
        W1h, (size_t)2048 * 2368,
        l1_b, 2048, nullptr,
        H1, 2048, (size_t)BROWS * 2048,
        2048, 2368);

    // L2: E2[e] = para[e] * elu(H1[e] @ W2[e]^T + b2[e])   K=2048, N=2368 (pad 2560)
    gemm_wide<true, float><<<dim3(10, 32, 8), 256, SHW>>>(
        H1, 2048, (size_t)BROWS * 2048,
        W2h, (size_t)2560 * 2048,
        l2_b, 2368, para,
        E2, 2368, (size_t)BROWS * 2368,
        2368, 2048);

    // expert sum -> bufC[:, :2368] (fp16)
    reduce_kernel<<<4096, 256>>>();

    // L3: bufD = fp16(elu(bufC @ W3^T + b3))   K=2496, N=2048
    gemm_wide<false, __half><<<dim3(8, 32, 1), 256, SHW>>>(
        bufC, 2496, (size_t)0, W3h, (size_t)0, l3_b, 0, nullptr,
        bufD, 2176, (size_t)0, 2048, 2496);

    // L4: bufE = fp16(elu(bufD @ W4^T + b4))   K=2176, N=2368 (pad 2560)
    gemm_wide<false, __half><<<dim3(10, 32, 1), 256, SHW>>>(
        bufD, 2176, (size_t)0, W4h, (size_t)0, l4_b, 0, nullptr,
        bufE, 2496, (size_t)0, 2368, 2176);

    // L5: out = elu(bufE @ W5^T + b5)   K=2496, N=256 (fp32 out)
    gemm_narrow<float><<<dim3(2, 32), 256, SHN>>>(
        bufE, 2496, W5h, l5_b, out, 256, 256, 2496);
}